// round 1
// baseline (speedup 1.0000x reference)
#include <cuda_runtime.h>
#include <math.h>

#define BB 4
#define LL 4096
#define DD 256
#define AA 64
#define BM 64
#define BN 64
#define PAD 68   // floats per smem row (64 + 4 pad, float4-aligned)

// Scratch for q,k,v projections: [B*L, A] each (4 MB each).
__device__ float g_q[BB * LL * AA];
__device__ float g_k[BB * LL * AA];
__device__ float g_v[BB * LL * AA];

// ---------------------------------------------------------------------------
// Kernel 1: fused QKV projection.
// x:[B*L, D] @ {Wq,Wk,Wv}:[D, A] -> g_q/g_k/g_v:[B*L, A]
// Block: 64 output rows x 192 output cols, 256 threads, 4x12 register tile.
// ---------------------------------------------------------------------------
__global__ __launch_bounds__(256) void qkv_proj_kernel(
    const float* __restrict__ x,
    const float* __restrict__ Wq,
    const float* __restrict__ Wk,
    const float* __restrict__ Wv)
{
    __shared__ float xs[32][64 + 4];    // [d][m] transposed x tile
    __shared__ float ws[32][192 + 4];   // [d][c] concat weights

    const int t  = threadIdx.x;
    const int ty = t >> 4;      // 0..15 -> row group
    const int tx = t & 15;      // 0..15 -> col group (12 cols each)
    const int m0 = blockIdx.x * 64;

    float acc[4][12];
#pragma unroll
    for (int i = 0; i < 4; i++)
#pragma unroll
        for (int j = 0; j < 12; j++) acc[i][j] = 0.f;

    for (int d0 = 0; d0 < DD; d0 += 32) {
        // Load x tile 64 rows x 32 d, transposed into xs[d][m].
#pragma unroll
        for (int i = 0; i < 8; i++) {
            int idx = t + i * 256;          // 0..2047
            int m = idx >> 5;
            int d = idx & 31;
            xs[d][m] = x[(size_t)(m0 + m) * DD + d0 + d];
        }
        // Load weights 32 d x 192 c (q|k|v concat).
#pragma unroll
        for (int i = 0; i < 24; i++) {
            int idx = t + i * 256;          // 0..6143
            int d = idx / 192;
            int c = idx - d * 192;
            float w;
            if (c < 64)       w = Wq[(d0 + d) * AA + c];
            else if (c < 128) w = Wk[(d0 + d) * AA + (c - 64)];
            else              w = Wv[(d0 + d) * AA + (c - 128)];
            ws[d][c] = w;
        }
        __syncthreads();

#pragma unroll
        for (int d = 0; d < 32; d++) {
            float a[4];
#pragma unroll
            for (int i = 0; i < 4; i++) a[i] = xs[d][ty * 4 + i];
            float bv[12];
#pragma unroll
            for (int j = 0; j < 12; j++) bv[j] = ws[d][tx * 12 + j];
#pragma unroll
            for (int i = 0; i < 4; i++)
#pragma unroll
                for (int j = 0; j < 12; j++)
                    acc[i][j] += a[i] * bv[j];
        }
        __syncthreads();
    }

    // Scatter to g_q / g_k / g_v.
#pragma unroll
    for (int i = 0; i < 4; i++) {
        size_t row = (size_t)(m0 + ty * 4 + i);
#pragma unroll
        for (int j = 0; j < 12; j++) {
            int c = tx * 12 + j;
            float v = acc[i][j];
            if (c < 64)       g_q[row * AA + c] = v;
            else if (c < 128) g_k[row * AA + (c - 64)] = v;
            else              g_v[row * AA + (c - 128)] = v;
        }
    }
}

// ---------------------------------------------------------------------------
// Kernel 2: causal flash attention, fp32.
// Grid: (L/BM, B). Block: 256 threads (ty 0..15 rows, tx 0..15 cols), each
// thread owns a 4x4 tile of S and of O. All smem natural row-major, PAD=68.
// P overlays the K tile region after S is consumed.
// ---------------------------------------------------------------------------
extern __shared__ float smem_dyn[];

__global__ __launch_bounds__(256) void attn_kernel(float* __restrict__ out)
{
    float* Qs  = smem_dyn;                 // [64][PAD]  Q tile
    float* KPs = smem_dyn + 64 * PAD;      // [64][PAD]  K tile, later P tile
    float* Vs  = smem_dyn + 2 * 64 * PAD;  // [64][PAD]  V tile

    const int t  = threadIdx.x;
    const int ty = t >> 4;                 // row group: rows m0..m0+3
    const int tx = t & 15;                 // col group: cols n0..n0+3
    const int m0 = ty * 4;
    const int n0 = tx * 4;

    // Heavy (late) q-tiles first to balance the second wave.
    const int qt = (int)gridDim.x - 1 - (int)blockIdx.x;
    const int b  = blockIdx.y;
    const int qbase = qt * BM;
    const size_t base = (size_t)b * LL * AA;

    // Load Q tile (64x64, coalesced float4).
#pragma unroll
    for (int i = 0; i < 4; i++) {
        int idx = t + i * 256;             // float4 index 0..1023
        int m = idx >> 4;                  // 16 float4 per row
        int a = (idx & 15) << 2;
        *(float4*)&Qs[m * PAD + a] =
            *(const float4*)&g_q[base + (size_t)(qbase + m) * AA + a];
    }

    float O[4][4];
    float mrow[4], lrow[4];
#pragma unroll
    for (int i = 0; i < 4; i++) {
        mrow[i] = -1e30f;
        lrow[i] = 0.f;
#pragma unroll
        for (int j = 0; j < 4; j++) O[i][j] = 0.f;
    }

    for (int jt = 0; jt <= qt; jt++) {
        const int kbase = jt * BN;
        __syncthreads();  // previous PV reads of KPs/Vs complete

        // Load K and V tiles (coalesced float4, no transpose needed).
#pragma unroll
        for (int i = 0; i < 4; i++) {
            int idx = t + i * 256;
            int n = idx >> 4;
            int a = (idx & 15) << 2;
            size_t g = base + (size_t)(kbase + n) * AA + a;
            *(float4*)&KPs[n * PAD + a] = *(const float4*)&g_k[g];
            *(float4*)&Vs[n * PAD + a]  = *(const float4*)&g_v[g];
        }
        __syncthreads();

        // S = Q K^T for this thread's 4x4. Q reads broadcast across tx;
        // K reads are distinct float4 per tx -> conflict-free.
        float S[4][4];
#pragma unroll
        for (int i = 0; i < 4; i++)
#pragma unroll
            for (int j = 0; j < 4; j++) S[i][j] = 0.f;

#pragma unroll
        for (int ab = 0; ab < AA; ab += 4) {
            float4 qv[4], kv[4];
#pragma unroll
            for (int i = 0; i < 4; i++) qv[i] = *(float4*)&Qs[(m0 + i) * PAD + ab];
#pragma unroll
            for (int j = 0; j < 4; j++) kv[j] = *(float4*)&KPs[(n0 + j) * PAD + ab];
#pragma unroll
            for (int i = 0; i < 4; i++)
#pragma unroll
                for (int j = 0; j < 4; j++) {
                    S[i][j] += qv[i].x * kv[j].x;
                    S[i][j] += qv[i].y * kv[j].y;
                    S[i][j] += qv[i].z * kv[j].z;
                    S[i][j] += qv[i].w * kv[j].w;
                }
        }

        // Causal mask only on the diagonal tile.
        if (jt == qt) {
#pragma unroll
            for (int i = 0; i < 4; i++)
#pragma unroll
                for (int j = 0; j < 4; j++)
                    if (n0 + j > m0 + i) S[i][j] = -1e30f;
        }

        // Online softmax. Row r = m0+i lives on the 16 lanes sharing ty,
        // which are a contiguous 16-lane half-warp group -> shfl_xor 1..8.
#pragma unroll
        for (int i = 0; i < 4; i++) {
            float mt = fmaxf(fmaxf(S[i][0], S[i][1]), fmaxf(S[i][2], S[i][3]));
            mt = fmaxf(mt, __shfl_xor_sync(0xffffffffu, mt, 1));
            mt = fmaxf(mt, __shfl_xor_sync(0xffffffffu, mt, 2));
            mt = fmaxf(mt, __shfl_xor_sync(0xffffffffu, mt, 4));
            mt = fmaxf(mt, __shfl_xor_sync(0xffffffffu, mt, 8));
            float mnew  = fmaxf(mrow[i], mt);
            float scale = __expf(mrow[i] - mnew);
            float rs = 0.f;
#pragma unroll
            for (int j = 0; j < 4; j++) {
                float p = __expf(S[i][j] - mnew);
                S[i][j] = p;                 // reuse S regs as P
                rs += p;
            }
            rs += __shfl_xor_sync(0xffffffffu, rs, 1);
            rs += __shfl_xor_sync(0xffffffffu, rs, 2);
            rs += __shfl_xor_sync(0xffffffffu, rs, 4);
            rs += __shfl_xor_sync(0xffffffffu, rs, 8);
            lrow[i] = lrow[i] * scale + rs;
            mrow[i] = mnew;
#pragma unroll
            for (int j = 0; j < 4; j++) O[i][j] *= scale;
        }

        __syncthreads();  // all S reads of K done -> safe to overwrite with P

        // Write P (natural layout, float4, conflict-free STS.128).
#pragma unroll
        for (int i = 0; i < 4; i++) {
            float4 p4 = make_float4(S[i][0], S[i][1], S[i][2], S[i][3]);
            *(float4*)&KPs[(m0 + i) * PAD + n0] = p4;
        }
        __syncthreads();

        // O += P V. P reads broadcast across tx; V reads distinct per tx.
#pragma unroll
        for (int nb = 0; nb < BN; nb += 4) {
            float4 pv[4], vv[4];
#pragma unroll
            for (int i = 0; i < 4; i++) pv[i] = *(float4*)&KPs[(m0 + i) * PAD + nb];
#pragma unroll
            for (int k = 0; k < 4; k++) vv[k] = *(float4*)&Vs[(nb + k) * PAD + n0];
#pragma unroll
            for (int i = 0; i < 4; i++) {
                O[i][0] += pv[i].x * vv[0].x + pv[i].y * vv[1].x + pv[i].z * vv[2].x + pv[i].w * vv[3].x;
                O[i][1] += pv[i].x * vv[0].y + pv[i].y * vv[1].y + pv[i].z * vv[2].y + pv[i].w * vv[3].y;
                O[i][2] += pv[i].x * vv[0].z + pv[i].y * vv[1].z + pv[i].z * vv[2].z + pv[i].w * vv[3].z;
                O[i][3] += pv[i].x * vv[0].w + pv[i].y * vv[1].w + pv[i].z * vv[2].w + pv[i].w * vv[3].w;
            }
        }
    }

    // Epilogue: normalize and store (A-cols owned by tx -> coalesced float4).
#pragma unroll
    for (int i = 0; i < 4; i++) {
        float inv = 1.f / lrow[i];
        size_t row = (size_t)(qbase + m0 + i);
        float4 o = make_float4(O[i][0] * inv, O[i][1] * inv,
                               O[i][2] * inv, O[i][3] * inv);
        *(float4*)&out[base + row * AA + n0] = o;
    }
}

// ---------------------------------------------------------------------------
extern "C" void kernel_launch(void* const* d_in, const int* in_sizes, int n_in,
                              void* d_out, int out_size)
{
    const float* x  = (const float*)d_in[0];
    const float* Wq = (const float*)d_in[1];
    const float* Wk = (const float*)d_in[2];
    const float* Wv = (const float*)d_in[3];
    float* out = (float*)d_out;

    // QKV projection: 16384 rows / 64 = 256 blocks.
    qkv_proj_kernel<<<BB * LL / 64, 256>>>(x, Wq, Wk, Wv);

    // Flash attention: 52224 B dynamic smem (> 48 KB static limit).
    const int smem_bytes = 3 * 64 * PAD * sizeof(float);
    cudaFuncSetAttribute(attn_kernel,
                         cudaFuncAttributeMaxDynamicSharedMemorySize, smem_bytes);
    dim3 grid(LL / BM, BB);
    attn_kernel<<<grid, 256, smem_bytes>>>(out);
}

// round 2
// speedup vs baseline: 1.3008x; 1.3008x over previous
#include <cuda_runtime.h>
#include <math.h>

#define BB 4
#define LL 4096
#define DD 256
#define AA 64
#define BM 64
#define BN 64
#define PAD 68   // floats per smem row (64 data + 4 pad; 272B, float4-aligned)

// Swizzle: float4-column rotation by (row>>2). Returns float offset in row.
// Makes stride-4-row accesses (kv loads: rows 4*tx+j) conflict-free:
// bank-group = (5*tx + j + a4) mod 8, and 5*tx is a permutation mod 8.
#define SWF(row, a4) (((((a4) + ((row) >> 2)) & 15)) << 2)

// Scratch for q,k,v projections: [B*L, A] each (4 MB each).
__device__ float g_q[BB * LL * AA];
__device__ float g_k[BB * LL * AA];
__device__ float g_v[BB * LL * AA];

// ---------------------------------------------------------------------------
// Kernel 1: fused QKV projection.
// x:[B*L, D] @ {Wq,Wk,Wv}:[D, A] -> g_q/g_k/g_v:[B*L, A]
// Block: 64 rows x (3 x 64) cols, 256 threads. Thread owns 4 rows x (4 cols
// in EACH of q,k,v)  -> no cross-matrix branches, float4 everywhere.
// ---------------------------------------------------------------------------
__global__ __launch_bounds__(256) void qkv_proj_kernel(
    const float* __restrict__ x,
    const float* __restrict__ Wq,
    const float* __restrict__ Wk,
    const float* __restrict__ Wv)
{
    __shared__ float xs[32 * 65];    // [d][m] transposed x tile, stride 65
    __shared__ float ws[32 * 196];   // [d][192] q|k|v concat, stride 196 (f4-aligned)

    const int t  = threadIdx.x;
    const int ty = t >> 4;      // 0..15 -> 4 rows each
    const int tx = t & 15;      // 0..15 -> 4 cols in each matrix
    const int m0 = blockIdx.x * 64;

    float acc[4][12];   // [row][q0..3 | k0..3 | v0..3]
#pragma unroll
    for (int i = 0; i < 4; i++)
#pragma unroll
        for (int j = 0; j < 12; j++) acc[i][j] = 0.f;

    for (int d0 = 0; d0 < DD; d0 += 32) {
        // x tile: 64 rows x 32 d, transposed into xs[d][m]. Coalesced LDG,
        // stride-65 rows -> conflict-free STS.32.
#pragma unroll
        for (int i = 0; i < 8; i++) {
            int idx = t + i * 256;          // 0..2047
            int m = idx >> 5;
            int d = idx & 31;
            xs[d * 65 + m] = x[(size_t)(m0 + m) * DD + d0 + d];
        }
        // Weights: 32 d x 192 c, float4 loads. 1536 f4 / 256 thr = 6 iters.
#pragma unroll
        for (int i = 0; i < 6; i++) {
            int idx = t + i * 256;          // 0..1535
            int mat = idx >> 9;             // 0,1,2
            int r   = idx & 511;
            int d   = r >> 4;
            int a4  = r & 15;
            const float* W = (mat == 0) ? Wq : (mat == 1) ? Wk : Wv;
            *(float4*)&ws[d * 196 + mat * 64 + a4 * 4] =
                *(const float4*)&W[(size_t)(d0 + d) * AA + a4 * 4];
        }
        __syncthreads();

#pragma unroll
        for (int d = 0; d < 32; d++) {
            float a[4];
#pragma unroll
            for (int i = 0; i < 4; i++) a[i] = xs[d * 65 + ty * 4 + i];
            float4 bq = *(float4*)&ws[d * 196 +       tx * 4];
            float4 bk = *(float4*)&ws[d * 196 +  64 + tx * 4];
            float4 bv = *(float4*)&ws[d * 196 + 128 + tx * 4];
#pragma unroll
            for (int i = 0; i < 4; i++) {
                acc[i][0] += a[i] * bq.x; acc[i][1] += a[i] * bq.y;
                acc[i][2] += a[i] * bq.z; acc[i][3] += a[i] * bq.w;
                acc[i][4] += a[i] * bk.x; acc[i][5] += a[i] * bk.y;
                acc[i][6] += a[i] * bk.z; acc[i][7] += a[i] * bk.w;
                acc[i][8] += a[i] * bv.x; acc[i][9] += a[i] * bv.y;
                acc[i][10]+= a[i] * bv.z; acc[i][11]+= a[i] * bv.w;
            }
        }
        __syncthreads();
    }

#pragma unroll
    for (int i = 0; i < 4; i++) {
        size_t row = (size_t)(m0 + ty * 4 + i);
        *(float4*)&g_q[row * AA + tx * 4] = make_float4(acc[i][0], acc[i][1], acc[i][2], acc[i][3]);
        *(float4*)&g_k[row * AA + tx * 4] = make_float4(acc[i][4], acc[i][5], acc[i][6], acc[i][7]);
        *(float4*)&g_v[row * AA + tx * 4] = make_float4(acc[i][8], acc[i][9], acc[i][10], acc[i][11]);
    }
}

// ---------------------------------------------------------------------------
// Kernel 2: causal flash attention, fp32.
// Grid: (L/BM, B). Block: 128 threads; ty=t>>4 (8 row groups of 8 rows),
// tx=t&15 (16 col groups of 4 cols). Thread tile 8x4. Swizzled smem.
// P overlays the K tile region after S is consumed.
// ---------------------------------------------------------------------------
extern __shared__ float smem_dyn[];

__global__ __launch_bounds__(128) void attn_kernel(float* __restrict__ out)
{
    float* Qs  = smem_dyn;                 // [64][PAD]  Q tile (swizzled)
    float* KPs = smem_dyn + 64 * PAD;      // [64][PAD]  K tile, later P tile
    float* Vs  = smem_dyn + 2 * 64 * PAD;  // [64][PAD]  V tile

    const int t  = threadIdx.x;
    const int ty = t >> 4;                 // 0..7
    const int tx = t & 15;                 // 0..15
    const int m0 = ty * 8;
    const int n0 = tx * 4;

    // Heavy (late) q-tiles first.
    const int qt = (int)gridDim.x - 1 - (int)blockIdx.x;
    const int b  = blockIdx.y;
    const int qbase = qt * BM;
    const size_t base = (size_t)b * LL * AA;

    // Load Q tile (64x64 = 1024 f4, 128 threads -> 8 iters). Coalesced LDG,
    // swizzled conflict-free STS.128.
#pragma unroll
    for (int i = 0; i < 8; i++) {
        int idx = t + i * 128;
        int m  = idx >> 4;
        int a4 = idx & 15;
        *(float4*)&Qs[m * PAD + SWF(m, a4)] =
            *(const float4*)&g_q[base + (size_t)(qbase + m) * AA + a4 * 4];
    }

    float O[8][4];
    float mrow[8], lrow[8];
#pragma unroll
    for (int i = 0; i < 8; i++) {
        mrow[i] = -1e30f;
        lrow[i] = 0.f;
#pragma unroll
        for (int j = 0; j < 4; j++) O[i][j] = 0.f;
    }

    for (int jt = 0; jt <= qt; jt++) {
        const int kbase = jt * BN;
        __syncthreads();  // previous PV reads of KPs/Vs complete

#pragma unroll
        for (int i = 0; i < 8; i++) {
            int idx = t + i * 128;
            int n  = idx >> 4;
            int a4 = idx & 15;
            size_t g = base + (size_t)(kbase + n) * AA + a4 * 4;
            int so = n * PAD + SWF(n, a4);
            *(float4*)&KPs[so] = *(const float4*)&g_k[g];
            *(float4*)&Vs[so]  = *(const float4*)&g_v[g];
        }
        __syncthreads();

        // S = Q K^T. kv: 4 distinct f4/lane, conflict-free via swizzle.
        // qv: broadcast within half-warp.
        float S[8][4];
#pragma unroll
        for (int i = 0; i < 8; i++)
#pragma unroll
            for (int j = 0; j < 4; j++) S[i][j] = 0.f;

#pragma unroll
        for (int ab4 = 0; ab4 < 16; ab4++) {
            float4 kv[4];
#pragma unroll
            for (int j = 0; j < 4; j++)
                kv[j] = *(float4*)&KPs[(n0 + j) * PAD + SWF(n0 + j, ab4)];
#pragma unroll
            for (int i = 0; i < 8; i++) {
                float4 qv = *(float4*)&Qs[(m0 + i) * PAD + SWF(m0 + i, ab4)];
#pragma unroll
                for (int j = 0; j < 4; j++) {
                    S[i][j] += qv.x * kv[j].x;
                    S[i][j] += qv.y * kv[j].y;
                    S[i][j] += qv.z * kv[j].z;
                    S[i][j] += qv.w * kv[j].w;
                }
            }
        }

        if (jt == qt) {
#pragma unroll
            for (int i = 0; i < 8; i++)
#pragma unroll
                for (int j = 0; j < 4; j++)
                    if (n0 + j > m0 + i) S[i][j] = -1e30f;
        }

        // Online softmax; row r=m0+i lives on a contiguous 16-lane group.
#pragma unroll
        for (int i = 0; i < 8; i++) {
            float mt = fmaxf(fmaxf(S[i][0], S[i][1]), fmaxf(S[i][2], S[i][3]));
            mt = fmaxf(mt, __shfl_xor_sync(0xffffffffu, mt, 1));
            mt = fmaxf(mt, __shfl_xor_sync(0xffffffffu, mt, 2));
            mt = fmaxf(mt, __shfl_xor_sync(0xffffffffu, mt, 4));
            mt = fmaxf(mt, __shfl_xor_sync(0xffffffffu, mt, 8));
            float mnew  = fmaxf(mrow[i], mt);
            float scale = __expf(mrow[i] - mnew);
            float rs = 0.f;
#pragma unroll
            for (int j = 0; j < 4; j++) {
                float p = __expf(S[i][j] - mnew);
                S[i][j] = p;
                rs += p;
            }
            rs += __shfl_xor_sync(0xffffffffu, rs, 1);
            rs += __shfl_xor_sync(0xffffffffu, rs, 2);
            rs += __shfl_xor_sync(0xffffffffu, rs, 4);
            rs += __shfl_xor_sync(0xffffffffu, rs, 8);
            lrow[i] = lrow[i] * scale + rs;
            mrow[i] = mnew;
#pragma unroll
            for (int j = 0; j < 4; j++) O[i][j] *= scale;
        }

        __syncthreads();  // all S reads of K done -> overwrite with P

        // Write P (f4 col index = tx; swizzled, conflict-free).
#pragma unroll
        for (int i = 0; i < 8; i++) {
            *(float4*)&KPs[(m0 + i) * PAD + SWF(m0 + i, tx)] =
                make_float4(S[i][0], S[i][1], S[i][2], S[i][3]);
        }
        __syncthreads();

        // O += P V. vv: distinct per tx (conflict-free); pv: broadcast.
#pragma unroll
        for (int nb4 = 0; nb4 < 16; nb4++) {
            float4 vv[4];
#pragma unroll
            for (int k = 0; k < 4; k++)
                vv[k] = *(float4*)&Vs[(nb4 * 4 + k) * PAD + SWF(nb4 * 4 + k, tx)];
#pragma unroll
            for (int i = 0; i < 8; i++) {
                float4 pv = *(float4*)&KPs[(m0 + i) * PAD + SWF(m0 + i, nb4)];
                O[i][0] += pv.x * vv[0].x + pv.y * vv[1].x + pv.z * vv[2].x + pv.w * vv[3].x;
                O[i][1] += pv.x * vv[0].y + pv.y * vv[1].y + pv.z * vv[2].y + pv.w * vv[3].y;
                O[i][2] += pv.x * vv[0].z + pv.y * vv[1].z + pv.z * vv[2].z + pv.w * vv[3].z;
                O[i][3] += pv.x * vv[0].w + pv.y * vv[1].w + pv.z * vv[2].w + pv.w * vv[3].w;
            }
        }
    }

    // Epilogue: normalize and store.
#pragma unroll
    for (int i = 0; i < 8; i++) {
        float inv = 1.f / lrow[i];
        size_t row = (size_t)(qbase + m0 + i);
        *(float4*)&out[base + row * AA + n0] =
            make_float4(O[i][0] * inv, O[i][1] * inv, O[i][2] * inv, O[i][3] * inv);
    }
}

// ---------------------------------------------------------------------------
extern "C" void kernel_launch(void* const* d_in, const int* in_sizes, int n_in,
                              void* d_out, int out_size)
{
    const float* x  = (const float*)d_in[0];
    const float* Wq = (const float*)d_in[1];
    const float* Wk = (const float*)d_in[2];
    const float* Wv = (const float*)d_in[3];
    float* out = (float*)d_out;

    qkv_proj_kernel<<<BB * LL / 64, 256>>>(x, Wq, Wk, Wv);

    const int smem_bytes = 3 * 64 * PAD * sizeof(float);  // 52224 B
    cudaFuncSetAttribute(attn_kernel,
                         cudaFuncAttributeMaxDynamicSharedMemorySize, smem_bytes);
    dim3 grid(LL / BM, BB);
    attn_kernel<<<grid, 128, smem_bytes>>>(out);
}

// round 3
// speedup vs baseline: 1.7741x; 1.3639x over previous
#include <cuda_runtime.h>
#include <math.h>

#define BB 4
#define LL 4096
#define DD 256
#define AA 64
#define PAD 72   // floats per smem row (288 B): row stride = 8 banks

// ---------------- f32x2 helpers (sm_103a packed fp32) ----------------------
__device__ __forceinline__ unsigned long long pk2(float a) {
    unsigned long long r; unsigned u = __float_as_uint(a);
    asm("mov.b64 %0, {%1, %1};" : "=l"(r) : "r"(u));
    return r;
}
__device__ __forceinline__ void fma2(unsigned long long& d,
                                     unsigned long long a, unsigned long long b) {
    asm("fma.rn.f32x2 %0, %1, %2, %0;" : "+l"(d) : "l"(a), "l"(b));
}
__device__ __forceinline__ void mul2(unsigned long long& d, unsigned long long a) {
    asm("mul.rn.f32x2 %0, %0, %1;" : "+l"(d) : "l"(a));
}
__device__ __forceinline__ void upk(unsigned long long v, float& x, float& y) {
    unsigned a, b;
    asm("mov.b64 {%0, %1}, %2;" : "=r"(a), "=r"(b) : "l"(v));
    x = __uint_as_float(a); y = __uint_as_float(b);
}

// Scratch for q,k,v projections: [B*L, A] each.
__device__ float g_q[BB * LL * AA];
__device__ float g_k[BB * LL * AA];
__device__ float g_v[BB * LL * AA];

// ---------------------------------------------------------------------------
// Kernel 1: fused QKV projection (unchanged from R2; ~12us).
// ---------------------------------------------------------------------------
__global__ __launch_bounds__(256) void qkv_proj_kernel(
    const float* __restrict__ x,
    const float* __restrict__ Wq,
    const float* __restrict__ Wk,
    const float* __restrict__ Wv)
{
    __shared__ float xs[32 * 65];
    __shared__ float ws[32 * 196];

    const int t  = threadIdx.x;
    const int ty = t >> 4;
    const int tx = t & 15;
    const int m0 = blockIdx.x * 64;

    float acc[4][12];
#pragma unroll
    for (int i = 0; i < 4; i++)
#pragma unroll
        for (int j = 0; j < 12; j++) acc[i][j] = 0.f;

    for (int d0 = 0; d0 < DD; d0 += 32) {
#pragma unroll
        for (int i = 0; i < 8; i++) {
            int idx = t + i * 256;
            int m = idx >> 5;
            int d = idx & 31;
            xs[d * 65 + m] = x[(size_t)(m0 + m) * DD + d0 + d];
        }
#pragma unroll
        for (int i = 0; i < 6; i++) {
            int idx = t + i * 256;
            int mat = idx >> 9;
            int r   = idx & 511;
            int d   = r >> 4;
            int a4  = r & 15;
            const float* W = (mat == 0) ? Wq : (mat == 1) ? Wk : Wv;
            *(float4*)&ws[d * 196 + mat * 64 + a4 * 4] =
                *(const float4*)&W[(size_t)(d0 + d) * AA + a4 * 4];
        }
        __syncthreads();

#pragma unroll
        for (int d = 0; d < 32; d++) {
            float a[4];
#pragma unroll
            for (int i = 0; i < 4; i++) a[i] = xs[d * 65 + ty * 4 + i];
            float4 bq = *(float4*)&ws[d * 196 +       tx * 4];
            float4 bk = *(float4*)&ws[d * 196 +  64 + tx * 4];
            float4 bv = *(float4*)&ws[d * 196 + 128 + tx * 4];
#pragma unroll
            for (int i = 0; i < 4; i++) {
                acc[i][0] += a[i] * bq.x; acc[i][1] += a[i] * bq.y;
                acc[i][2] += a[i] * bq.z; acc[i][3] += a[i] * bq.w;
                acc[i][4] += a[i] * bk.x; acc[i][5] += a[i] * bk.y;
                acc[i][6] += a[i] * bk.z; acc[i][7] += a[i] * bk.w;
                acc[i][8] += a[i] * bv.x; acc[i][9] += a[i] * bv.y;
                acc[i][10]+= a[i] * bv.z; acc[i][11]+= a[i] * bv.w;
            }
        }
        __syncthreads();
    }

#pragma unroll
    for (int i = 0; i < 4; i++) {
        size_t row = (size_t)(m0 + ty * 4 + i);
        *(float4*)&g_q[row * AA + tx * 4] = make_float4(acc[i][0], acc[i][1], acc[i][2], acc[i][3]);
        *(float4*)&g_k[row * AA + tx * 4] = make_float4(acc[i][4], acc[i][5], acc[i][6], acc[i][7]);
        *(float4*)&g_v[row * AA + tx * 4] = make_float4(acc[i][8], acc[i][9], acc[i][10], acc[i][11]);
    }
}

// ---------------------------------------------------------------------------
// Kernel 2: causal flash attention, fp32 with f32x2 packed FMA.
// CTA c handles q-half-tiles c (rows c*32..) and 127-c (rows (127-c)*32..):
// every CTA performs ~65 half-tile iterations -> perfect balance, one wave.
// Smem: Qs natural (lo rows 0-31, hi 32-63); KPs = K transposed [ab][n]
// (xor-f4-swizzled), reused as P [qrow][n]; Vs natural.
// ---------------------------------------------------------------------------
extern __shared__ float smem_dyn[];

// h = 0 -> hi half (smem row offset 32), h = 1 -> lo half (offset 0).
#define HOFF(h) ((h) ? 0 : 32)

template<int NH>
__device__ __forceinline__ void tile_step(
    const float* __restrict__ Qs, float* __restrict__ KPs,
    const float* __restrict__ Vs,
    unsigned long long (&O01)[2][2], unsigned long long (&O23)[2][2],
    float (&mr)[2][2], float (&lr)[2][2],
    int ty, int tx, int kbase, const int* rowg0, const bool* msk)
{
    unsigned long long S01[NH][2], S23[NH][2];
#pragma unroll
    for (int h = 0; h < NH; h++)
#pragma unroll
        for (int i = 0; i < 2; i++) { S01[h][i] = 0ull; S23[h][i] = 0ull; }

    // ---- S = Q K^T ----
#pragma unroll
    for (int ab4 = 0; ab4 < 16; ab4++) {
        float4 qv[NH][2];
#pragma unroll
        for (int h = 0; h < NH; h++)
#pragma unroll
            for (int i = 0; i < 2; i++)
                qv[h][i] = *(const float4*)&Qs[(HOFF(h) + ty * 2 + i) * PAD + ab4 * 4];
#pragma unroll
        for (int e = 0; e < 4; e++) {
            const int ab = ab4 * 4 + e;
            const ulonglong2 kv =
                *(const ulonglong2*)&KPs[ab * PAD + ((tx ^ (ab & 15)) << 2)];
#pragma unroll
            for (int h = 0; h < NH; h++)
#pragma unroll
                for (int i = 0; i < 2; i++) {
                    unsigned long long qq = pk2(((const float*)&qv[h][i])[e]);
                    fma2(S01[h][i], qq, kv.x);
                    fma2(S23[h][i], qq, kv.y);
                }
        }
    }

    __syncthreads();   // S reads of K done -> KPs may become P

    // ---- mask + online softmax + P store ----
#pragma unroll
    for (int h = 0; h < NH; h++)
#pragma unroll
        for (int i = 0; i < 2; i++) {
            float s0, s1, s2, s3;
            upk(S01[h][i], s0, s1);
            upk(S23[h][i], s2, s3);
            if (msk[h]) {
                int rg = rowg0[h] + ty * 2 + i;
                int cg = kbase + tx * 4;
                if (cg + 0 > rg) s0 = -1e30f;
                if (cg + 1 > rg) s1 = -1e30f;
                if (cg + 2 > rg) s2 = -1e30f;
                if (cg + 3 > rg) s3 = -1e30f;
            }
            float mt = fmaxf(fmaxf(s0, s1), fmaxf(s2, s3));
            mt = fmaxf(mt, __shfl_xor_sync(0xffffffffu, mt, 1));
            mt = fmaxf(mt, __shfl_xor_sync(0xffffffffu, mt, 2));
            mt = fmaxf(mt, __shfl_xor_sync(0xffffffffu, mt, 4));
            mt = fmaxf(mt, __shfl_xor_sync(0xffffffffu, mt, 8));
            float mnew = fmaxf(mr[h][i], mt);
            float sc   = __expf(mr[h][i] - mnew);
            s0 = __expf(s0 - mnew); s1 = __expf(s1 - mnew);
            s2 = __expf(s2 - mnew); s3 = __expf(s3 - mnew);
            float rs = s0 + s1 + s2 + s3;
            rs += __shfl_xor_sync(0xffffffffu, rs, 1);
            rs += __shfl_xor_sync(0xffffffffu, rs, 2);
            rs += __shfl_xor_sync(0xffffffffu, rs, 4);
            rs += __shfl_xor_sync(0xffffffffu, rs, 8);
            lr[h][i] = lr[h][i] * sc + rs;
            mr[h][i] = mnew;
            unsigned long long scp = pk2(sc);
            mul2(O01[h][i], scp);
            mul2(O23[h][i], scp);
            int r = HOFF(h) + ty * 2 + i;
            *(float4*)&KPs[r * PAD + ((tx ^ (r & 15)) << 2)] =
                make_float4(s0, s1, s2, s3);
        }

    __syncthreads();   // P visible

    // ---- O += P V ----
#pragma unroll
    for (int nb4 = 0; nb4 < 16; nb4++) {
        float4 pv[NH][2];
#pragma unroll
        for (int h = 0; h < NH; h++)
#pragma unroll
            for (int i = 0; i < 2; i++) {
                int r = HOFF(h) + ty * 2 + i;
                pv[h][i] = *(const float4*)&KPs[r * PAD + ((nb4 ^ (r & 15)) << 2)];
            }
#pragma unroll
        for (int e = 0; e < 4; e++) {
            const int n = nb4 * 4 + e;
            const ulonglong2 vv = *(const ulonglong2*)&Vs[n * PAD + tx * 4];
#pragma unroll
            for (int h = 0; h < NH; h++)
#pragma unroll
                for (int i = 0; i < 2; i++) {
                    unsigned long long pp = pk2(((const float*)&pv[h][i])[e]);
                    fma2(O01[h][i], pp, vv.x);
                    fma2(O23[h][i], pp, vv.y);
                }
        }
    }
}

__global__ __launch_bounds__(256, 2) void attn_kernel(float* __restrict__ out)
{
    float* Qs  = smem_dyn;                 // [64][PAD] lo rows 0-31, hi 32-63
    float* KPs = smem_dyn + 64 * PAD;      // K^T [ab][n] then P [qrow][n]
    float* Vs  = smem_dyn + 128 * PAD;     // V natural [n][a]

    const int t  = threadIdx.x;
    const int ty = t >> 4;                 // 0..15 -> rows ty*2, ty*2+1 per half
    const int tx = t & 15;                 // 0..15 -> cols tx*4..tx*4+3

    const int c = blockIdx.x;              // 0..63
    const int b = blockIdx.y;
    const int lo_base = c * 32;
    const int hi_base = (127 - c) * 32;
    const int jt_lo = c >> 1;
    const int jt_hi = (127 - c) >> 1;
    const size_t base = (size_t)b * LL * AA;
    const int rowg0[2] = { hi_base, lo_base };

    // Load Q: rows 0-31 <- lo tile, 32-63 <- hi tile (coalesced f4).
#pragma unroll
    for (int i = 0; i < 4; i++) {
        int idx = t + i * 256;             // 0..1023 f4
        int m  = idx >> 4;
        int a4 = idx & 15;
        int grow = (m < 32) ? (lo_base + m) : (hi_base + m - 32);
        *(float4*)&Qs[m * PAD + a4 * 4] =
            *(const float4*)&g_q[base + (size_t)grow * AA + a4 * 4];
    }

    unsigned long long O01[2][2], O23[2][2];
    float mr[2][2], lr[2][2];
#pragma unroll
    for (int h = 0; h < 2; h++)
#pragma unroll
        for (int i = 0; i < 2; i++) {
            O01[h][i] = 0ull; O23[h][i] = 0ull;
            mr[h][i] = -1e30f; lr[h][i] = 0.f;
        }

    for (int jt = 0; jt <= jt_hi; jt++) {
        const int kbase = jt * 64;
        __syncthreads();   // prior PV reads of KPs/Vs complete

        // Load K (transposed + swizzled scatter) and V (natural).
#pragma unroll
        for (int i = 0; i < 4; i++) {
            int idx = t + i * 256;
            int n  = idx >> 4;
            int a4 = idx & 15;
            size_t g = base + (size_t)(kbase + n) * AA + a4 * 4;
            float4 kf = *(const float4*)&g_k[g];
            float4 vf = *(const float4*)&g_v[g];
            int ab0 = a4 * 4;
            int n4 = n >> 2, nl = n & 3;
            KPs[(ab0 + 0) * PAD + ((n4 ^ ((ab0 + 0) & 15)) << 2) + nl] = kf.x;
            KPs[(ab0 + 1) * PAD + ((n4 ^ ((ab0 + 1) & 15)) << 2) + nl] = kf.y;
            KPs[(ab0 + 2) * PAD + ((n4 ^ ((ab0 + 2) & 15)) << 2) + nl] = kf.z;
            KPs[(ab0 + 3) * PAD + ((n4 ^ ((ab0 + 3) & 15)) << 2) + nl] = kf.w;
            *(float4*)&Vs[n * PAD + a4 * 4] = vf;
        }
        __syncthreads();

        const bool msk[2] = { jt == jt_hi, jt == jt_lo };
        if (jt <= jt_lo)
            tile_step<2>(Qs, KPs, Vs, O01, O23, mr, lr, ty, tx, kbase, rowg0, msk);
        else
            tile_step<1>(Qs, KPs, Vs, O01, O23, mr, lr, ty, tx, kbase, rowg0, msk);
    }

    // Epilogue: normalize + store.
#pragma unroll
    for (int h = 0; h < 2; h++)
#pragma unroll
        for (int i = 0; i < 2; i++) {
            float inv = 1.f / lr[h][i];
            float o0, o1, o2, o3;
            upk(O01[h][i], o0, o1);
            upk(O23[h][i], o2, o3);
            size_t row = (size_t)(rowg0[h] + ty * 2 + i);
            *(float4*)&out[base + row * AA + tx * 4] =
                make_float4(o0 * inv, o1 * inv, o2 * inv, o3 * inv);
        }
}

// ---------------------------------------------------------------------------
extern "C" void kernel_launch(void* const* d_in, const int* in_sizes, int n_in,
                              void* d_out, int out_size)
{
    const float* x  = (const float*)d_in[0];
    const float* Wq = (const float*)d_in[1];
    const float* Wk = (const float*)d_in[2];
    const float* Wv = (const float*)d_in[3];
    float* out = (float*)d_out;

    qkv_proj_kernel<<<BB * LL / 64, 256>>>(x, Wq, Wk, Wv);

    const int smem_bytes = 3 * 64 * PAD * sizeof(float);  // 55296 B
    cudaFuncSetAttribute(attn_kernel,
                         cudaFuncAttributeMaxDynamicSharedMemorySize, smem_bytes);
    dim3 grid(64, BB);
    attn_kernel<<<grid, 256, smem_bytes>>>(out);
}

// round 5
// speedup vs baseline: 6.0365x; 3.4025x over previous
#include <cuda_runtime.h>
#include <cuda_bf16.h>
#include <stdint.h>

#define BB 4
#define LL 4096
#define DD 256
#define AA 64
#define INFF 1e30f

// ------------------------- bf16 split scratch ------------------------------
__device__ __align__(256) __nv_bfloat16 g_qhi[BB * LL * AA];
__device__ __align__(256) __nv_bfloat16 g_qlo[BB * LL * AA];
__device__ __align__(256) __nv_bfloat16 g_khi[BB * LL * AA];
__device__ __align__(256) __nv_bfloat16 g_klo[BB * LL * AA];
__device__ __align__(256) __nv_bfloat16 g_vhi[BB * LL * AA];
__device__ __align__(256) __nv_bfloat16 g_vlo[BB * LL * AA];

// ------------------------- PTX helpers -------------------------------------
__device__ __forceinline__ uint32_t smem_u32(const void* p) {
    uint32_t a;
    asm("{ .reg .u64 t; cvta.to.shared.u64 t, %1; cvt.u32.u64 %0, t; }"
        : "=r"(a) : "l"(p));
    return a;
}

// byte offset of (row r, 16B-col c4) with SW128-style XOR swizzle (128B rows)
#define SWZI(r, c4) (((r) << 7) + ((((c4) ^ ((r) & 7))) << 4))

__device__ __forceinline__ void ldsm4(unsigned r[4], uint32_t a) {
    asm volatile("ldmatrix.sync.aligned.m8n8.x4.shared.b16 {%0,%1,%2,%3}, [%4];"
        : "=r"(r[0]), "=r"(r[1]), "=r"(r[2]), "=r"(r[3]) : "r"(a));
}
__device__ __forceinline__ void ldsm4t(unsigned r[4], uint32_t a) {
    asm volatile("ldmatrix.sync.aligned.m8n8.x4.trans.shared.b16 {%0,%1,%2,%3}, [%4];"
        : "=r"(r[0]), "=r"(r[1]), "=r"(r[2]), "=r"(r[3]) : "r"(a));
}
__device__ __forceinline__ void mma16816(float d[4], const unsigned a[4],
                                         const unsigned b[2]) {
    asm volatile("mma.sync.aligned.m16n8k16.row.col.f32.bf16.bf16.f32 "
        "{%0,%1,%2,%3}, {%4,%5,%6,%7}, {%8,%9}, {%0,%1,%2,%3};"
        : "+f"(d[0]), "+f"(d[1]), "+f"(d[2]), "+f"(d[3])
        : "r"(a[0]), "r"(a[1]), "r"(a[2]), "r"(a[3]), "r"(b[0]), "r"(b[1]));
}
#define CP16(d, s) asm volatile("cp.async.cg.shared.global [%0], [%1], 16;" :: "r"(d), "l"(s))
#define CP_COMMIT() asm volatile("cp.async.commit_group;" ::: "memory")
#define CP_WAIT0()  asm volatile("cp.async.wait_group 0;" ::: "memory")

// pack hi bf16x2, return lo residual bf16x2 via out-param
__device__ __forceinline__ unsigned pkhl(float a, float b, unsigned& lo) {
    __nv_bfloat162 h2 = __floats2bfloat162_rn(a, b);
    __nv_bfloat162 l2 = __floats2bfloat162_rn(
        a - __bfloat162float(__low2bfloat16(h2)),
        b - __bfloat162float(__high2bfloat16(h2)));
    lo = *(unsigned*)&l2;
    return *(unsigned*)&h2;
}

// ---------------------------------------------------------------------------
// Kernel 1: fused QKV projection -> bf16 hi/lo splits (all natural layout).
// ---------------------------------------------------------------------------
__global__ __launch_bounds__(256) void qkv_proj_kernel(
    const float* __restrict__ x,
    const float* __restrict__ Wq,
    const float* __restrict__ Wk,
    const float* __restrict__ Wv)
{
    __shared__ float xs[32 * 65];
    __shared__ float ws[32 * 196];

    const int t  = threadIdx.x;
    const int ty = t >> 4;
    const int tx = t & 15;
    const int m0 = blockIdx.x * 64;

    float acc[4][12];
#pragma unroll
    for (int i = 0; i < 4; i++)
#pragma unroll
        for (int j = 0; j < 12; j++) acc[i][j] = 0.f;

    for (int d0 = 0; d0 < DD; d0 += 32) {
#pragma unroll
        for (int i = 0; i < 8; i++) {
            int idx = t + i * 256;
            int m = idx >> 5;
            int d = idx & 31;
            xs[d * 65 + m] = x[(size_t)(m0 + m) * DD + d0 + d];
        }
#pragma unroll
        for (int i = 0; i < 6; i++) {
            int idx = t + i * 256;
            int mat = idx >> 9;
            int r   = idx & 511;
            int d   = r >> 4;
            int a4  = r & 15;
            const float* W = (mat == 0) ? Wq : (mat == 1) ? Wk : Wv;
            *(float4*)&ws[d * 196 + mat * 64 + a4 * 4] =
                *(const float4*)&W[(size_t)(d0 + d) * AA + a4 * 4];
        }
        __syncthreads();

#pragma unroll
        for (int d = 0; d < 32; d++) {
            float a[4];
#pragma unroll
            for (int i = 0; i < 4; i++) a[i] = xs[d * 65 + ty * 4 + i];
            float4 bq = *(float4*)&ws[d * 196 +       tx * 4];
            float4 bk = *(float4*)&ws[d * 196 +  64 + tx * 4];
            float4 bv = *(float4*)&ws[d * 196 + 128 + tx * 4];
#pragma unroll
            for (int i = 0; i < 4; i++) {
                acc[i][0] += a[i] * bq.x; acc[i][1] += a[i] * bq.y;
                acc[i][2] += a[i] * bq.z; acc[i][3] += a[i] * bq.w;
                acc[i][4] += a[i] * bk.x; acc[i][5] += a[i] * bk.y;
                acc[i][6] += a[i] * bk.z; acc[i][7] += a[i] * bk.w;
                acc[i][8] += a[i] * bv.x; acc[i][9] += a[i] * bv.y;
                acc[i][10]+= a[i] * bv.z; acc[i][11]+= a[i] * bv.w;
            }
        }
        __syncthreads();
    }

#pragma unroll
    for (int i = 0; i < 4; i++) {
        size_t row = (size_t)(m0 + ty * 4 + i);
#pragma unroll
        for (int j = 0; j < 4; j++) {
            int a = tx * 4 + j;
            float q = acc[i][j], k = acc[i][4 + j], v = acc[i][8 + j];
            __nv_bfloat16 qh = __float2bfloat16(q);
            __nv_bfloat16 kh = __float2bfloat16(k);
            __nv_bfloat16 vh = __float2bfloat16(v);
            size_t ri = row * AA + a;
            g_qhi[ri] = qh;
            g_qlo[ri] = __float2bfloat16(q - __bfloat162float(qh));
            g_khi[ri] = kh;
            g_klo[ri] = __float2bfloat16(k - __bfloat162float(kh));
            g_vhi[ri] = vh;
            g_vlo[ri] = __float2bfloat16(v - __bfloat162float(vh));
        }
    }
}

// ---------------------------------------------------------------------------
// Kernel 2: causal flash attention via mma.sync (split-bf16, 3 passes/GEMM).
// CTA = 4 warps, processes q-tile pair (c, 63-c): exactly 65 half-steps each.
// ---------------------------------------------------------------------------
// SMEM layout (bytes):
#define SM_Q   0        // Qhi [128 rows][128B] @0; Qlo @ +16384
#define SM_KH  32768    // K hi: 2 bufs x 64 x 128B
#define SM_KL  49152
#define SM_VH  65536
#define SM_VL  81920
#define SM_TOTAL 98304

extern __shared__ char smc[];

__device__ __forceinline__ void prefetch_kv(uint32_t sb, int buf, size_t gkb, int t)
{
#pragma unroll
    for (int i = 0; i < 4; i++) {
        int idx = t + i * 128;          // 0..511
        int r  = idx >> 3;
        int c4 = idx & 7;
        size_t g = gkb + (size_t)r * AA + c4 * 8;
        uint32_t so = (uint32_t)(buf * 8192 + SWZI(r, c4));
        CP16(sb + SM_KH + so, g_khi + g);
        CP16(sb + SM_KL + so, g_klo + g);
        CP16(sb + SM_VH + so, g_vhi + g);
        CP16(sb + SM_VL + so, g_vlo + g);
    }
}

template<int NH>
__device__ __forceinline__ void attn_step(
    uint32_t sb, int buf, int kb, int w, int lane,
    const int (&qoff)[2], const int (&rb)[2], const bool (&diag)[2],
    float (&O)[2][8][4], float (&mr)[2][2], float (&lr)[2][2])
{
    float S[NH][8][4];
#pragma unroll
    for (int h = 0; h < NH; h++)
#pragma unroll
        for (int nt = 0; nt < 8; nt++)
#pragma unroll
            for (int e = 0; e < 4; e++) S[h][nt][e] = 0.f;

    const uint32_t khb = sb + SM_KH + buf * 8192;
    const uint32_t klb = sb + SM_KL + buf * 8192;

    // ---- S = Q K^T (3 split passes fused per K-fragment load) ----
#pragma unroll
    for (int kt = 0; kt < 4; kt++) {
        unsigned qh[NH][4], ql[NH][4];
#pragma unroll
        for (int h = 0; h < NH; h++) {
            uint32_t qa = sb + SM_Q +
                SWZI(qoff[h] + w * 16 + (lane & 15), kt * 2 + (lane >> 4));
            ldsm4(qh[h], qa);
            ldsm4(ql[h], qa + 16384);
        }
#pragma unroll
        for (int np = 0; np < 4; np++) {
            int r  = np * 16 + ((lane >> 4) << 3) + (lane & 7);
            int c4 = kt * 2 + ((lane >> 3) & 1);
            unsigned kh[4], kl[4];
            ldsm4(kh, khb + SWZI(r, c4));
            ldsm4(kl, klb + SWZI(r, c4));
#pragma unroll
            for (int h = 0; h < NH; h++)
#pragma unroll
                for (int ntl = 0; ntl < 2; ntl++) {
                    mma16816(S[h][2 * np + ntl], qh[h], kh + 2 * ntl);
                    mma16816(S[h][2 * np + ntl], ql[h], kh + 2 * ntl);
                    mma16816(S[h][2 * np + ntl], qh[h], kl + 2 * ntl);
                }
        }
    }

    // ---- mask + online softmax (rows g, g+8 per thread) ----
    const int g  = lane >> 2;
    const int tq = lane & 3;
#pragma unroll
    for (int h = 0; h < NH; h++) {
        int r0 = rb[h] + g, r1 = r0 + 8;
        if (diag[h]) {
#pragma unroll
            for (int nt = 0; nt < 8; nt++) {
                int col = kb + nt * 8 + 2 * tq;
                if (col     > r0) S[h][nt][0] = -INFF;
                if (col + 1 > r0) S[h][nt][1] = -INFF;
                if (col     > r1) S[h][nt][2] = -INFF;
                if (col + 1 > r1) S[h][nt][3] = -INFF;
            }
        }
        float m0 = -INFF, m1 = -INFF;
#pragma unroll
        for (int nt = 0; nt < 8; nt++) {
            m0 = fmaxf(m0, fmaxf(S[h][nt][0], S[h][nt][1]));
            m1 = fmaxf(m1, fmaxf(S[h][nt][2], S[h][nt][3]));
        }
        m0 = fmaxf(m0, __shfl_xor_sync(0xffffffffu, m0, 1));
        m0 = fmaxf(m0, __shfl_xor_sync(0xffffffffu, m0, 2));
        m1 = fmaxf(m1, __shfl_xor_sync(0xffffffffu, m1, 1));
        m1 = fmaxf(m1, __shfl_xor_sync(0xffffffffu, m1, 2));
        float mn0 = fmaxf(mr[h][0], m0), mn1 = fmaxf(mr[h][1], m1);
        float sc0 = __expf(mr[h][0] - mn0), sc1 = __expf(mr[h][1] - mn1);
        mr[h][0] = mn0; mr[h][1] = mn1;
        float s0 = 0.f, s1 = 0.f;
#pragma unroll
        for (int nt = 0; nt < 8; nt++) {
            S[h][nt][0] = __expf(S[h][nt][0] - mn0);
            S[h][nt][1] = __expf(S[h][nt][1] - mn0);
            S[h][nt][2] = __expf(S[h][nt][2] - mn1);
            S[h][nt][3] = __expf(S[h][nt][3] - mn1);
            s0 += S[h][nt][0] + S[h][nt][1];
            s1 += S[h][nt][2] + S[h][nt][3];
            O[h][nt][0] *= sc0; O[h][nt][1] *= sc0;
            O[h][nt][2] *= sc1; O[h][nt][3] *= sc1;
        }
        s0 += __shfl_xor_sync(0xffffffffu, s0, 1);
        s0 += __shfl_xor_sync(0xffffffffu, s0, 2);
        s1 += __shfl_xor_sync(0xffffffffu, s1, 1);
        s1 += __shfl_xor_sync(0xffffffffu, s1, 2);
        lr[h][0] = lr[h][0] * sc0 + s0;
        lr[h][1] = lr[h][1] * sc1 + s1;
    }

    // ---- O += P V (S frags repacked in-register as P A-frags) ----
    const uint32_t vhb = sb + SM_VH + buf * 8192;
    const uint32_t vlb = sb + SM_VL + buf * 8192;
#pragma unroll
    for (int kt = 0; kt < 4; kt++) {
        unsigned ph[NH][4], pl[NH][4];
#pragma unroll
        for (int h = 0; h < NH; h++) {
            ph[h][0] = pkhl(S[h][2*kt  ][0], S[h][2*kt  ][1], pl[h][0]);
            ph[h][1] = pkhl(S[h][2*kt  ][2], S[h][2*kt  ][3], pl[h][1]);
            ph[h][2] = pkhl(S[h][2*kt+1][0], S[h][2*kt+1][1], pl[h][2]);
            ph[h][3] = pkhl(S[h][2*kt+1][2], S[h][2*kt+1][3], pl[h][3]);
        }
#pragma unroll
        for (int np = 0; np < 4; np++) {
            int r  = kt * 16 + (((lane >> 3) & 1) << 3) + (lane & 7);
            int c4 = np * 2 + (lane >> 4);
            unsigned vh4[4], vl4[4];
            ldsm4t(vh4, vhb + SWZI(r, c4));
            ldsm4t(vl4, vlb + SWZI(r, c4));
#pragma unroll
            for (int h = 0; h < NH; h++)
#pragma unroll
                for (int ntl = 0; ntl < 2; ntl++) {
                    mma16816(O[h][2 * np + ntl], ph[h], vh4 + 2 * ntl);
                    mma16816(O[h][2 * np + ntl], pl[h], vh4 + 2 * ntl);
                    mma16816(O[h][2 * np + ntl], ph[h], vl4 + 2 * ntl);
                }
        }
    }
}

__global__ __launch_bounds__(128) void attn_kernel(float* __restrict__ out)
{
    const uint32_t sb = smem_u32(smc);
    const int t    = threadIdx.x;
    const int w    = t >> 5;
    const int lane = t & 31;

    const int c = blockIdx.x;              // pair id 0..31
    const int b = blockIdx.y;
    const int lo_tile = c, hi_tile = 63 - c;
    const int nsteps  = 64 - c;            // jt = 0 .. 63-c
    const size_t gbase = (size_t)b * LL * AA;

    const int qoff[2] = { 64, 0 };                                   // smem rows
    const int rb[2]   = { hi_tile * 64 + w * 16, lo_tile * 64 + w * 16 };

    // Prefetch first K/V tile, then load Q (both tiles, hi+lo) synchronously.
    prefetch_kv(sb, 0, gbase, t);
    CP_COMMIT();
#pragma unroll
    for (int i = 0; i < 8; i++) {
        int idx = t + i * 128;             // 0..1023
        int r  = idx >> 3;
        int c4 = idx & 7;
        int tile = (r < 64) ? lo_tile : hi_tile;
        size_t g = gbase + ((size_t)tile * 64 + (r & 63)) * AA + c4 * 8;
        int so = SWZI(r, c4);
        *(uint4*)(smc + SM_Q + so)         = *(const uint4*)&g_qhi[g];
        *(uint4*)(smc + SM_Q + 16384 + so) = *(const uint4*)&g_qlo[g];
    }

    float O[2][8][4];
    float mr[2][2], lr[2][2];
#pragma unroll
    for (int h = 0; h < 2; h++) {
        mr[h][0] = mr[h][1] = -INFF;
        lr[h][0] = lr[h][1] = 0.f;
#pragma unroll
        for (int nt = 0; nt < 8; nt++)
#pragma unroll
            for (int e = 0; e < 4; e++) O[h][nt][e] = 0.f;
    }

    for (int jt = 0; jt < nsteps; jt++) {
        const int buf = jt & 1;
        CP_WAIT0();
        __syncthreads();
        if (jt + 1 < nsteps) {
            prefetch_kv(sb, buf ^ 1, gbase + (size_t)(jt + 1) * 64 * AA, t);
            CP_COMMIT();
        }
        const int kb = jt * 64;
        const bool diag[2] = { jt == nsteps - 1, jt == c };
        if (jt <= c)
            attn_step<2>(sb, buf, kb, w, lane, qoff, rb, diag, O, mr, lr);
        else
            attn_step<1>(sb, buf, kb, w, lane, qoff, rb, diag, O, mr, lr);
        __syncthreads();   // step's smem reads done before next overwrite/wait
    }

    // ---- epilogue ----
    const int g  = lane >> 2;
    const int tq = lane & 3;
#pragma unroll
    for (int h = 0; h < 2; h++) {
        float i0 = 1.f / lr[h][0], i1 = 1.f / lr[h][1];
        size_t r0 = (size_t)(rb[h] + g), r1 = r0 + 8;
#pragma unroll
        for (int nt = 0; nt < 8; nt++) {
            *(float2*)&out[gbase + r0 * AA + nt * 8 + 2 * tq] =
                make_float2(O[h][nt][0] * i0, O[h][nt][1] * i0);
            *(float2*)&out[gbase + r1 * AA + nt * 8 + 2 * tq] =
                make_float2(O[h][nt][2] * i1, O[h][nt][3] * i1);
        }
    }
}

// ---------------------------------------------------------------------------
extern "C" void kernel_launch(void* const* d_in, const int* in_sizes, int n_in,
                              void* d_out, int out_size)
{
    const float* x  = (const float*)d_in[0];
    const float* Wq = (const float*)d_in[1];
    const float* Wk = (const float*)d_in[2];
    const float* Wv = (const float*)d_in[3];
    float* out = (float*)d_out;

    qkv_proj_kernel<<<BB * LL / 64, 256>>>(x, Wq, Wk, Wv);

    cudaFuncSetAttribute(attn_kernel,
                         cudaFuncAttributeMaxDynamicSharedMemorySize, SM_TOTAL);
    dim3 grid(32, BB);
    attn_kernel<<<grid, 128, SM_TOTAL>>>(out);
}

// round 6
// speedup vs baseline: 6.3599x; 1.0536x over previous
#include <cuda_runtime.h>
#include <cuda_bf16.h>
#include <stdint.h>

#define BB 4
#define LL 4096
#define DD 256
#define AA 64
#define INFF 1e30f
#define LOG2E 1.4426950408889634f

typedef unsigned long long ull;

// ------------------------- bf16 split scratch ------------------------------
__device__ __align__(256) __nv_bfloat16 g_qhi[BB * LL * AA];
__device__ __align__(256) __nv_bfloat16 g_qlo[BB * LL * AA];
__device__ __align__(256) __nv_bfloat16 g_khi[BB * LL * AA];  // pre-scaled by log2e
__device__ __align__(256) __nv_bfloat16 g_klo[BB * LL * AA];
__device__ __align__(256) __nv_bfloat16 g_vhi[BB * LL * AA];
__device__ __align__(256) __nv_bfloat16 g_vlo[BB * LL * AA];

// ------------------------- PTX helpers -------------------------------------
__device__ __forceinline__ uint32_t smem_u32(const void* p) {
    uint32_t a;
    asm("{ .reg .u64 t; cvta.to.shared.u64 t, %1; cvt.u32.u64 %0, t; }"
        : "=r"(a) : "l"(p));
    return a;
}

#define SWZI(r, c4) (((r) << 7) + ((((c4) ^ ((r) & 7))) << 4))

__device__ __forceinline__ void ldsm4(unsigned r[4], uint32_t a) {
    asm volatile("ldmatrix.sync.aligned.m8n8.x4.shared.b16 {%0,%1,%2,%3}, [%4];"
        : "=r"(r[0]), "=r"(r[1]), "=r"(r[2]), "=r"(r[3]) : "r"(a));
}
__device__ __forceinline__ void ldsm4t(unsigned r[4], uint32_t a) {
    asm volatile("ldmatrix.sync.aligned.m8n8.x4.trans.shared.b16 {%0,%1,%2,%3}, [%4];"
        : "=r"(r[0]), "=r"(r[1]), "=r"(r[2]), "=r"(r[3]) : "r"(a));
}
__device__ __forceinline__ void mma16816(float d[4], const unsigned a[4],
                                         const unsigned b[2]) {
    asm volatile("mma.sync.aligned.m16n8k16.row.col.f32.bf16.bf16.f32 "
        "{%0,%1,%2,%3}, {%4,%5,%6,%7}, {%8,%9}, {%0,%1,%2,%3};"
        : "+f"(d[0]), "+f"(d[1]), "+f"(d[2]), "+f"(d[3])
        : "r"(a[0]), "r"(a[1]), "r"(a[2]), "r"(a[3]), "r"(b[0]), "r"(b[1]));
}
#define CP16(d, s) asm volatile("cp.async.cg.shared.global [%0], [%1], 16;" :: "r"(d), "l"(s))
#define CP_COMMIT() asm volatile("cp.async.commit_group;" ::: "memory")
#define CP_WAIT0()  asm volatile("cp.async.wait_group 0;" ::: "memory")

__device__ __forceinline__ float ex2f(float x) {
    float r;
    asm("ex2.approx.ftz.f32 %0, %1;" : "=f"(r) : "f"(x));
    return r;
}
__device__ __forceinline__ ull pk2(float a) {
    ull r; unsigned u = __float_as_uint(a);
    asm("mov.b64 %0, {%1, %1};" : "=l"(r) : "r"(u));
    return r;
}
__device__ __forceinline__ void fma2(ull& d, ull a, ull b) {
    asm("fma.rn.f32x2 %0, %1, %2, %0;" : "+l"(d) : "l"(a), "l"(b));
}
__device__ __forceinline__ void upk(ull v, float& x, float& y) {
    unsigned a, b;
    asm("mov.b64 {%0, %1}, %2;" : "=r"(a), "=r"(b) : "l"(v));
    x = __uint_as_float(a); y = __uint_as_float(b);
}
// pack hi bf16x2, return lo residual bf16x2 via out-param
__device__ __forceinline__ unsigned pkhl(float a, float b, unsigned& lo) {
    __nv_bfloat162 h2 = __floats2bfloat162_rn(a, b);
    __nv_bfloat162 l2 = __floats2bfloat162_rn(
        a - __bfloat162float(__low2bfloat16(h2)),
        b - __bfloat162float(__high2bfloat16(h2)));
    lo = *(unsigned*)&l2;
    return *(unsigned*)&h2;
}

// ---------------------------------------------------------------------------
// Kernel 1: fused QKV projection (f32x2 inner loop) -> bf16 hi/lo splits.
// K is pre-scaled by log2e so attention softmax uses raw ex2.
// ---------------------------------------------------------------------------
__global__ __launch_bounds__(256) void qkv_proj_kernel(
    const float* __restrict__ x,
    const float* __restrict__ Wq,
    const float* __restrict__ Wk,
    const float* __restrict__ Wv)
{
    __shared__ float xs[32 * 65];
    __shared__ float ws[32 * 196];

    const int t  = threadIdx.x;
    const int ty = t >> 4;
    const int tx = t & 15;
    const int m0 = blockIdx.x * 64;

    ull acc2[4][6];   // [row][q01,q23,k01,k23,v01,v23] packed f32x2
#pragma unroll
    for (int i = 0; i < 4; i++)
#pragma unroll
        for (int j = 0; j < 6; j++) acc2[i][j] = 0ull;

    for (int d0 = 0; d0 < DD; d0 += 32) {
#pragma unroll
        for (int i = 0; i < 8; i++) {
            int idx = t + i * 256;
            int m = idx >> 5;
            int d = idx & 31;
            xs[d * 65 + m] = x[(size_t)(m0 + m) * DD + d0 + d];
        }
#pragma unroll
        for (int i = 0; i < 6; i++) {
            int idx = t + i * 256;
            int mat = idx >> 9;
            int r   = idx & 511;
            int d   = r >> 4;
            int a4  = r & 15;
            const float* W = (mat == 0) ? Wq : (mat == 1) ? Wk : Wv;
            *(float4*)&ws[d * 196 + mat * 64 + a4 * 4] =
                *(const float4*)&W[(size_t)(d0 + d) * AA + a4 * 4];
        }
        __syncthreads();

#pragma unroll
        for (int d = 0; d < 32; d++) {
            ull ap[4];
#pragma unroll
            for (int i = 0; i < 4; i++) ap[i] = pk2(xs[d * 65 + ty * 4 + i]);
            const ull* bq = (const ull*)&ws[d * 196 +       tx * 4];
            const ull* bk = (const ull*)&ws[d * 196 +  64 + tx * 4];
            const ull* bv = (const ull*)&ws[d * 196 + 128 + tx * 4];
            ull q0 = bq[0], q1 = bq[1];
            ull k0 = bk[0], k1 = bk[1];
            ull v0 = bv[0], v1 = bv[1];
#pragma unroll
            for (int i = 0; i < 4; i++) {
                fma2(acc2[i][0], ap[i], q0); fma2(acc2[i][1], ap[i], q1);
                fma2(acc2[i][2], ap[i], k0); fma2(acc2[i][3], ap[i], k1);
                fma2(acc2[i][4], ap[i], v0); fma2(acc2[i][5], ap[i], v1);
            }
        }
        __syncthreads();
    }

#pragma unroll
    for (int i = 0; i < 4; i++) {
        size_t row = (size_t)(m0 + ty * 4 + i);
        float q[4], k[4], v[4];
        upk(acc2[i][0], q[0], q[1]); upk(acc2[i][1], q[2], q[3]);
        upk(acc2[i][2], k[0], k[1]); upk(acc2[i][3], k[2], k[3]);
        upk(acc2[i][4], v[0], v[1]); upk(acc2[i][5], v[2], v[3]);
#pragma unroll
        for (int j = 0; j < 4; j++) {
            int a = tx * 4 + j;
            float qf = q[j], kf = k[j] * LOG2E, vf = v[j];
            __nv_bfloat16 qh = __float2bfloat16(qf);
            __nv_bfloat16 kh = __float2bfloat16(kf);
            __nv_bfloat16 vh = __float2bfloat16(vf);
            size_t ri = row * AA + a;
            g_qhi[ri] = qh;
            g_qlo[ri] = __float2bfloat16(qf - __bfloat162float(qh));
            g_khi[ri] = kh;
            g_klo[ri] = __float2bfloat16(kf - __bfloat162float(kh));
            g_vhi[ri] = vh;
            g_vlo[ri] = __float2bfloat16(vf - __bfloat162float(vh));
        }
    }
}

// ---------------------------------------------------------------------------
// Kernel 2: causal flash attention via mma.sync (split-bf16, 3 passes/GEMM).
// CTA = 4 warps, q-tile pair (c, 63-c): exactly 65 half-steps each.
// Softmax exp/pack interleaved with PV MMAs at 16-col chunk granularity.
// ---------------------------------------------------------------------------
#define SM_Q   0        // Qhi [128 rows][128B] @0; Qlo @ +16384
#define SM_KH  32768
#define SM_KL  49152
#define SM_VH  65536
#define SM_VL  81920
#define SM_TOTAL 98304

extern __shared__ char smc[];

__device__ __forceinline__ void prefetch_kv(uint32_t sb, int buf, size_t gkb, int t)
{
#pragma unroll
    for (int i = 0; i < 4; i++) {
        int idx = t + i * 128;
        int r  = idx >> 3;
        int c4 = idx & 7;
        size_t g = gkb + (size_t)r * AA + c4 * 8;
        uint32_t so = (uint32_t)(buf * 8192 + SWZI(r, c4));
        CP16(sb + SM_KH + so, g_khi + g);
        CP16(sb + SM_KL + so, g_klo + g);
        CP16(sb + SM_VH + so, g_vhi + g);
        CP16(sb + SM_VL + so, g_vlo + g);
    }
}

template<int NH>
__device__ __forceinline__ void attn_step(
    uint32_t sb, int buf, int kb, int w, int lane,
    const int (&qoff)[2], const int (&rb)[2], const bool (&diag)[2],
    float (&O)[2][8][4], float (&mr)[2][2], float (&lr)[2][2])
{
    float S[NH][8][4];
#pragma unroll
    for (int h = 0; h < NH; h++)
#pragma unroll
        for (int nt = 0; nt < 8; nt++)
#pragma unroll
            for (int e = 0; e < 4; e++) S[h][nt][e] = 0.f;

    const uint32_t khb = sb + SM_KH + buf * 8192;
    const uint32_t klb = sb + SM_KL + buf * 8192;

    // ---- S = Q K^T: pass-outermost per (kt,np) so same-acc MMAs sit 4 apart
#pragma unroll
    for (int kt = 0; kt < 4; kt++) {
        unsigned qh[NH][4], ql[NH][4];
#pragma unroll
        for (int h = 0; h < NH; h++) {
            uint32_t qa = sb + SM_Q +
                SWZI(qoff[h] + w * 16 + (lane & 15), kt * 2 + (lane >> 4));
            ldsm4(qh[h], qa);
            ldsm4(ql[h], qa + 16384);
        }
#pragma unroll
        for (int np = 0; np < 4; np++) {
            int r  = np * 16 + ((lane >> 4) << 3) + (lane & 7);
            int c4 = kt * 2 + ((lane >> 3) & 1);
            unsigned kh[4], kl[4];
            ldsm4(kh, khb + SWZI(r, c4));
            ldsm4(kl, klb + SWZI(r, c4));
#pragma unroll
            for (int h = 0; h < NH; h++)
#pragma unroll
                for (int ntl = 0; ntl < 2; ntl++)
                    mma16816(S[h][2 * np + ntl], qh[h], kh + 2 * ntl);
#pragma unroll
            for (int h = 0; h < NH; h++)
#pragma unroll
                for (int ntl = 0; ntl < 2; ntl++)
                    mma16816(S[h][2 * np + ntl], ql[h], kh + 2 * ntl);
#pragma unroll
            for (int h = 0; h < NH; h++)
#pragma unroll
                for (int ntl = 0; ntl < 2; ntl++)
                    mma16816(S[h][2 * np + ntl], qh[h], kl + 2 * ntl);
        }
    }

    // ---- mask + row max + O rescale (full-row dependencies only) ----
    const int g  = lane >> 2;
    const int tq = lane & 3;
    float mn[NH][2], sc[NH][2];
#pragma unroll
    for (int h = 0; h < NH; h++) {
        int r0 = rb[h] + g, r1 = r0 + 8;
        if (diag[h]) {
#pragma unroll
            for (int nt = 0; nt < 8; nt++) {
                int col = kb + nt * 8 + 2 * tq;
                if (col     > r0) S[h][nt][0] = -INFF;
                if (col + 1 > r0) S[h][nt][1] = -INFF;
                if (col     > r1) S[h][nt][2] = -INFF;
                if (col + 1 > r1) S[h][nt][3] = -INFF;
            }
        }
        float m0 = -INFF, m1 = -INFF;
#pragma unroll
        for (int nt = 0; nt < 8; nt++) {
            m0 = fmaxf(m0, fmaxf(S[h][nt][0], S[h][nt][1]));
            m1 = fmaxf(m1, fmaxf(S[h][nt][2], S[h][nt][3]));
        }
        m0 = fmaxf(m0, __shfl_xor_sync(0xffffffffu, m0, 1));
        m0 = fmaxf(m0, __shfl_xor_sync(0xffffffffu, m0, 2));
        m1 = fmaxf(m1, __shfl_xor_sync(0xffffffffu, m1, 1));
        m1 = fmaxf(m1, __shfl_xor_sync(0xffffffffu, m1, 2));
        mn[h][0] = fmaxf(mr[h][0], m0);
        mn[h][1] = fmaxf(mr[h][1], m1);
        sc[h][0] = ex2f(mr[h][0] - mn[h][0]);
        sc[h][1] = ex2f(mr[h][1] - mn[h][1]);
        mr[h][0] = mn[h][0]; mr[h][1] = mn[h][1];
#pragma unroll
        for (int nt = 0; nt < 8; nt++) {
            O[h][nt][0] *= sc[h][0]; O[h][nt][1] *= sc[h][0];
            O[h][nt][2] *= sc[h][1]; O[h][nt][3] *= sc[h][1];
        }
    }

    // ---- interleaved exp/pack + PV MMAs, 16-col chunks ----
    const uint32_t vhb = sb + SM_VH + buf * 8192;
    const uint32_t vlb = sb + SM_VL + buf * 8192;
    float rs[NH][2];
#pragma unroll
    for (int h = 0; h < NH; h++) { rs[h][0] = 0.f; rs[h][1] = 0.f; }

#pragma unroll
    for (int kt = 0; kt < 4; kt++) {
        unsigned ph[NH][4], pl[NH][4];
#pragma unroll
        for (int h = 0; h < NH; h++) {
            float e00 = ex2f(S[h][2*kt  ][0] - mn[h][0]);
            float e01 = ex2f(S[h][2*kt  ][1] - mn[h][0]);
            float e02 = ex2f(S[h][2*kt  ][2] - mn[h][1]);
            float e03 = ex2f(S[h][2*kt  ][3] - mn[h][1]);
            float e10 = ex2f(S[h][2*kt+1][0] - mn[h][0]);
            float e11 = ex2f(S[h][2*kt+1][1] - mn[h][0]);
            float e12 = ex2f(S[h][2*kt+1][2] - mn[h][1]);
            float e13 = ex2f(S[h][2*kt+1][3] - mn[h][1]);
            rs[h][0] += (e00 + e01) + (e10 + e11);
            rs[h][1] += (e02 + e03) + (e12 + e13);
            ph[h][0] = pkhl(e00, e01, pl[h][0]);
            ph[h][1] = pkhl(e02, e03, pl[h][1]);
            ph[h][2] = pkhl(e10, e11, pl[h][2]);
            ph[h][3] = pkhl(e12, e13, pl[h][3]);
        }
#pragma unroll
        for (int np = 0; np < 4; np++) {
            int r  = kt * 16 + (((lane >> 3) & 1) << 3) + (lane & 7);
            int c4 = np * 2 + (lane >> 4);
            unsigned vh4[4], vl4[4];
            ldsm4t(vh4, vhb + SWZI(r, c4));
            ldsm4t(vl4, vlb + SWZI(r, c4));
#pragma unroll
            for (int h = 0; h < NH; h++)
#pragma unroll
                for (int ntl = 0; ntl < 2; ntl++)
                    mma16816(O[h][2 * np + ntl], ph[h], vh4 + 2 * ntl);
#pragma unroll
            for (int h = 0; h < NH; h++)
#pragma unroll
                for (int ntl = 0; ntl < 2; ntl++)
                    mma16816(O[h][2 * np + ntl], pl[h], vh4 + 2 * ntl);
#pragma unroll
            for (int h = 0; h < NH; h++)
#pragma unroll
                for (int ntl = 0; ntl < 2; ntl++)
                    mma16816(O[h][2 * np + ntl], ph[h], vl4 + 2 * ntl);
        }
    }

    // ---- deferred row-sum reductions + l update ----
#pragma unroll
    for (int h = 0; h < NH; h++) {
        float s0 = rs[h][0], s1 = rs[h][1];
        s0 += __shfl_xor_sync(0xffffffffu, s0, 1);
        s0 += __shfl_xor_sync(0xffffffffu, s0, 2);
        s1 += __shfl_xor_sync(0xffffffffu, s1, 1);
        s1 += __shfl_xor_sync(0xffffffffu, s1, 2);
        lr[h][0] = lr[h][0] * sc[h][0] + s0;
        lr[h][1] = lr[h][1] * sc[h][1] + s1;
    }
}

__global__ __launch_bounds__(128) void attn_kernel(float* __restrict__ out)
{
    const uint32_t sb = smem_u32(smc);
    const int t    = threadIdx.x;
    const int w    = t >> 5;
    const int lane = t & 31;

    const int c = blockIdx.x;              // pair id 0..31
    const int b = blockIdx.y;
    const int lo_tile = c, hi_tile = 63 - c;
    const int nsteps  = 64 - c;
    const size_t gbase = (size_t)b * LL * AA;

    const int qoff[2] = { 64, 0 };
    const int rb[2]   = { hi_tile * 64 + w * 16, lo_tile * 64 + w * 16 };

    prefetch_kv(sb, 0, gbase, t);
    CP_COMMIT();
#pragma unroll
    for (int i = 0; i < 8; i++) {
        int idx = t + i * 128;
        int r  = idx >> 3;
        int c4 = idx & 7;
        int tile = (r < 64) ? lo_tile : hi_tile;
        size_t g = gbase + ((size_t)tile * 64 + (r & 63)) * AA + c4 * 8;
        int so = SWZI(r, c4);
        *(uint4*)(smc + SM_Q + so)         = *(const uint4*)&g_qhi[g];
        *(uint4*)(smc + SM_Q + 16384 + so) = *(const uint4*)&g_qlo[g];
    }

    float O[2][8][4];
    float mr[2][2], lr[2][2];
#pragma unroll
    for (int h = 0; h < 2; h++) {
        mr[h][0] = mr[h][1] = -INFF;
        lr[h][0] = lr[h][1] = 0.f;
#pragma unroll
        for (int nt = 0; nt < 8; nt++)
#pragma unroll
            for (int e = 0; e < 4; e++) O[h][nt][e] = 0.f;
    }

    for (int jt = 0; jt < nsteps; jt++) {
        const int buf = jt & 1;
        CP_WAIT0();
        __syncthreads();
        if (jt + 1 < nsteps) {
            prefetch_kv(sb, buf ^ 1, gbase + (size_t)(jt + 1) * 64 * AA, t);
            CP_COMMIT();
        }
        const int kb = jt * 64;
        const bool diag[2] = { jt == nsteps - 1, jt == c };
        if (jt <= c)
            attn_step<2>(sb, buf, kb, w, lane, qoff, rb, diag, O, mr, lr);
        else
            attn_step<1>(sb, buf, kb, w, lane, qoff, rb, diag, O, mr, lr);
        __syncthreads();
    }

    // ---- epilogue ----
    const int g  = lane >> 2;
    const int tq = lane & 3;
#pragma unroll
    for (int h = 0; h < 2; h++) {
        float i0 = 1.f / lr[h][0], i1 = 1.f / lr[h][1];
        size_t r0 = (size_t)(rb[h] + g), r1 = r0 + 8;
#pragma unroll
        for (int nt = 0; nt < 8; nt++) {
            *(float2*)&out[gbase + r0 * AA + nt * 8 + 2 * tq] =
                make_float2(O[h][nt][0] * i0, O[h][nt][1] * i0);
            *(float2*)&out[gbase + r1 * AA + nt * 8 + 2 * tq] =
                make_float2(O[h][nt][2] * i1, O[h][nt][3] * i1);
        }
    }
}

// ---------------------------------------------------------------------------
extern "C" void kernel_launch(void* const* d_in, const int* in_sizes, int n_in,
                              void* d_out, int out_size)
{
    const float* x  = (const float*)d_in[0];
    const float* Wq = (const float*)d_in[1];
    const float* Wk = (const float*)d_in[2];
    const float* Wv = (const float*)d_in[3];
    float* out = (float*)d_out;

    qkv_proj_kernel<<<BB * LL / 64, 256>>>(x, Wq, Wk, Wv);

    cudaFuncSetAttribute(attn_kernel,
                         cudaFuncAttributeMaxDynamicSharedMemorySize, SM_TOTAL);
    dim3 grid(32, BB);
    attn_kernel<<<grid, 128, SM_TOTAL>>>(out);
}

// round 7
// speedup vs baseline: 7.1250x; 1.1203x over previous
#include <cuda_runtime.h>
#include <cuda_fp16.h>
#include <stdint.h>

#define BB 4
#define LL 4096
#define DD 256
#define AA 64
#define INFF 1e30f
#define LOG2E 1.4426950408889634f

typedef unsigned long long ull;

// ------------------------- fp16 split scratch ------------------------------
__device__ __align__(256) __half g_qhi[BB * LL * AA];
__device__ __align__(256) __half g_qlo[BB * LL * AA];
__device__ __align__(256) __half g_khi[BB * LL * AA];  // pre-scaled by log2e
__device__ __align__(256) __half g_klo[BB * LL * AA];
__device__ __align__(256) __half g_vhi[BB * LL * AA];  // single fp16

// ------------------------- PTX helpers -------------------------------------
__device__ __forceinline__ uint32_t smem_u32(const void* p) {
    uint32_t a;
    asm("{ .reg .u64 t; cvta.to.shared.u64 t, %1; cvt.u32.u64 %0, t; }"
        : "=r"(a) : "l"(p));
    return a;
}

#define SWZI(r, c4) (((r) << 7) + ((((c4) ^ ((r) & 7))) << 4))

__device__ __forceinline__ void ldsm4(unsigned r[4], uint32_t a) {
    asm volatile("ldmatrix.sync.aligned.m8n8.x4.shared.b16 {%0,%1,%2,%3}, [%4];"
        : "=r"(r[0]), "=r"(r[1]), "=r"(r[2]), "=r"(r[3]) : "r"(a));
}
__device__ __forceinline__ void ldsm4t(unsigned r[4], uint32_t a) {
    asm volatile("ldmatrix.sync.aligned.m8n8.x4.trans.shared.b16 {%0,%1,%2,%3}, [%4];"
        : "=r"(r[0]), "=r"(r[1]), "=r"(r[2]), "=r"(r[3]) : "r"(a));
}
__device__ __forceinline__ void mma16816(float d[4], const unsigned a[4],
                                         const unsigned b[2]) {
    asm volatile("mma.sync.aligned.m16n8k16.row.col.f32.f16.f16.f32 "
        "{%0,%1,%2,%3}, {%4,%5,%6,%7}, {%8,%9}, {%0,%1,%2,%3};"
        : "+f"(d[0]), "+f"(d[1]), "+f"(d[2]), "+f"(d[3])
        : "r"(a[0]), "r"(a[1]), "r"(a[2]), "r"(a[3]), "r"(b[0]), "r"(b[1]));
}
#define CP16(d, s) asm volatile("cp.async.cg.shared.global [%0], [%1], 16;" :: "r"(d), "l"(s))
#define CP_COMMIT() asm volatile("cp.async.commit_group;" ::: "memory")
#define CP_WAIT0()  asm volatile("cp.async.wait_group 0;" ::: "memory")

__device__ __forceinline__ float ex2f(float x) {
    float r;
    asm("ex2.approx.ftz.f32 %0, %1;" : "=f"(r) : "f"(x));
    return r;
}
__device__ __forceinline__ ull pk2(float a) {
    ull r; unsigned u = __float_as_uint(a);
    asm("mov.b64 %0, {%1, %1};" : "=l"(r) : "r"(u));
    return r;
}
__device__ __forceinline__ void fma2(ull& d, ull a, ull b) {
    asm("fma.rn.f32x2 %0, %1, %2, %0;" : "+l"(d) : "l"(a), "l"(b));
}
__device__ __forceinline__ void upk(ull v, float& x, float& y) {
    unsigned a, b;
    asm("mov.b64 {%0, %1}, %2;" : "=r"(a), "=r"(b) : "l"(v));
    x = __uint_as_float(a); y = __uint_as_float(b);
}
// pack hi fp16x2, return lo residual fp16x2 via out-param
__device__ __forceinline__ unsigned pkhl(float a, float b, unsigned& lo) {
    __half2 h2 = __floats2half2_rn(a, b);
    float2 hf = __half22float2(h2);
    __half2 l2 = __floats2half2_rn(a - hf.x, b - hf.y);
    lo = *(unsigned*)&l2;
    return *(unsigned*)&h2;
}

// ---------------------------------------------------------------------------
// Kernel 1: fused QKV projection (f32x2 inner loop) -> fp16 splits.
// ---------------------------------------------------------------------------
__global__ __launch_bounds__(256) void qkv_proj_kernel(
    const float* __restrict__ x,
    const float* __restrict__ Wq,
    const float* __restrict__ Wk,
    const float* __restrict__ Wv)
{
    __shared__ float xs[32 * 65];
    __shared__ float ws[32 * 196];

    const int t  = threadIdx.x;
    const int ty = t >> 4;
    const int tx = t & 15;
    const int m0 = blockIdx.x * 64;

    ull acc2[4][6];
#pragma unroll
    for (int i = 0; i < 4; i++)
#pragma unroll
        for (int j = 0; j < 6; j++) acc2[i][j] = 0ull;

    for (int d0 = 0; d0 < DD; d0 += 32) {
#pragma unroll
        for (int i = 0; i < 8; i++) {
            int idx = t + i * 256;
            int m = idx >> 5;
            int d = idx & 31;
            xs[d * 65 + m] = x[(size_t)(m0 + m) * DD + d0 + d];
        }
#pragma unroll
        for (int i = 0; i < 6; i++) {
            int idx = t + i * 256;
            int mat = idx >> 9;
            int r   = idx & 511;
            int d   = r >> 4;
            int a4  = r & 15;
            const float* W = (mat == 0) ? Wq : (mat == 1) ? Wk : Wv;
            *(float4*)&ws[d * 196 + mat * 64 + a4 * 4] =
                *(const float4*)&W[(size_t)(d0 + d) * AA + a4 * 4];
        }
        __syncthreads();

#pragma unroll
        for (int d = 0; d < 32; d++) {
            ull ap[4];
#pragma unroll
            for (int i = 0; i < 4; i++) ap[i] = pk2(xs[d * 65 + ty * 4 + i]);
            const ull* bq = (const ull*)&ws[d * 196 +       tx * 4];
            const ull* bk = (const ull*)&ws[d * 196 +  64 + tx * 4];
            const ull* bv = (const ull*)&ws[d * 196 + 128 + tx * 4];
            ull q0 = bq[0], q1 = bq[1];
            ull k0 = bk[0], k1 = bk[1];
            ull v0 = bv[0], v1 = bv[1];
#pragma unroll
            for (int i = 0; i < 4; i++) {
                fma2(acc2[i][0], ap[i], q0); fma2(acc2[i][1], ap[i], q1);
                fma2(acc2[i][2], ap[i], k0); fma2(acc2[i][3], ap[i], k1);
                fma2(acc2[i][4], ap[i], v0); fma2(acc2[i][5], ap[i], v1);
            }
        }
        __syncthreads();
    }

#pragma unroll
    for (int i = 0; i < 4; i++) {
        size_t row = (size_t)(m0 + ty * 4 + i);
        float q[4], k[4], v[4];
        upk(acc2[i][0], q[0], q[1]); upk(acc2[i][1], q[2], q[3]);
        upk(acc2[i][2], k[0], k[1]); upk(acc2[i][3], k[2], k[3]);
        upk(acc2[i][4], v[0], v[1]); upk(acc2[i][5], v[2], v[3]);
#pragma unroll
        for (int j = 0; j < 4; j++) {
            int a = tx * 4 + j;
            float qf = q[j], kf = k[j] * LOG2E;
            __half qh = __float2half(qf);
            __half kh = __float2half(kf);
            size_t ri = row * AA + a;
            g_qhi[ri] = qh;
            g_qlo[ri] = __float2half(qf - __half2float(qh));
            g_khi[ri] = kh;
            g_klo[ri] = __float2half(kf - __half2float(kh));
            g_vhi[ri] = __float2half(v[j]);
        }
    }
}

// ---------------------------------------------------------------------------
// Kernel 2: causal flash attention via fp16 mma.sync.
// 256 CTAs (64-row q-tile each), 4 warps, warp = 16 rows.
// S: 3-pass hi/lo split. PV: 2 passes, P split in regs, V single fp16.
// bid->tile map balances SM loads under classic placement LUT[bid%148].
// ---------------------------------------------------------------------------
#define SM_QH  0
#define SM_QL  8192
#define SM_KH  16384   // 2 bufs x 8KB
#define SM_KL  32768
#define SM_VH  49152
#define SM_TOTAL 65536

extern __shared__ char smc[];

__device__ __forceinline__ void prefetch_kv(uint32_t sb, int buf, size_t gkb, int t)
{
#pragma unroll
    for (int i = 0; i < 4; i++) {
        int idx = t + i * 128;          // 0..511
        int r  = idx >> 3;
        int c4 = idx & 7;
        size_t g = gkb + (size_t)r * AA + c4 * 8;
        uint32_t so = (uint32_t)(buf * 8192 + SWZI(r, c4));
        CP16(sb + SM_KH + so, g_khi + g);
        CP16(sb + SM_KL + so, g_klo + g);
        CP16(sb + SM_VH + so, g_vhi + g);
    }
}

__global__ __launch_bounds__(128, 2) void attn_kernel(float* __restrict__ out)
{
    const uint32_t sb = smem_u32(smc);
    const int t    = threadIdx.x;
    const int w    = t >> 5;
    const int lane = t & 31;

    // bid -> (tile, b): SM-pair (bid, bid+148) loads sum to 65 or 55 steps;
    // single-CTA SMs (bids 108..147) get mid tiles (41..50 steps).
    const int bid = blockIdx.x;
    int tile, b;
    if (bid < 56)       { tile = bid >> 2;              b = bid & 3; }
    else if (bid < 108) { tile = 14 + ((bid - 56) >> 2); b = (bid - 56) & 3; }
    else if (bid < 148) { tile = 40 + ((bid - 108) >> 2); b = (bid - 108) & 3; }
    else if (bid < 204) { tile = 63 - ((bid - 148) >> 2); b = (bid - 148) & 3; }
    else                { tile = 39 - ((bid - 204) >> 2); b = (bid - 204) & 3; }

    const size_t gbase = (size_t)b * LL * AA;
    const int rb = tile * 64 + w * 16;     // this warp's first q row

    prefetch_kv(sb, 0, gbase, t);
    CP_COMMIT();

    // Load Q tile (64 rows x 64 fp16, hi+lo).
#pragma unroll
    for (int i = 0; i < 4; i++) {
        int idx = t + i * 128;             // 0..511
        int r  = idx >> 3;
        int c4 = idx & 7;
        size_t g = gbase + (size_t)(tile * 64 + r) * AA + c4 * 8;
        int so = SWZI(r, c4);
        *(uint4*)(smc + SM_QH + so) = *(const uint4*)&g_qhi[g];
        *(uint4*)(smc + SM_QL + so) = *(const uint4*)&g_qlo[g];
    }

    float O[8][4];
    float mr[2], lr[2];
    mr[0] = mr[1] = -INFF;
    lr[0] = lr[1] = 0.f;
#pragma unroll
    for (int nt = 0; nt < 8; nt++)
#pragma unroll
        for (int e = 0; e < 4; e++) O[nt][e] = 0.f;

    const int g  = lane >> 2;
    const int tq = lane & 3;

    for (int jt = 0; jt <= tile; jt++) {
        const int buf = jt & 1;
        CP_WAIT0();
        __syncthreads();
        if (jt < tile) {
            prefetch_kv(sb, buf ^ 1, gbase + (size_t)(jt + 1) * 64 * AA, t);
            CP_COMMIT();
        }
        const int kb = jt * 64;
        const bool diag = (jt == tile);

        float S[8][4];
#pragma unroll
        for (int nt = 0; nt < 8; nt++)
#pragma unroll
            for (int e = 0; e < 4; e++) S[nt][e] = 0.f;

        const uint32_t khb = sb + SM_KH + buf * 8192;
        const uint32_t klb = sb + SM_KL + buf * 8192;

        // ---- S = Q K^T (3 split passes) ----
#pragma unroll
        for (int kt = 0; kt < 4; kt++) {
            unsigned qh4[4], ql4[4];
            uint32_t qa = sb + SM_QH +
                SWZI(w * 16 + (lane & 15), kt * 2 + (lane >> 4));
            ldsm4(qh4, qa);
            ldsm4(ql4, qa + 8192);
#pragma unroll
            for (int np = 0; np < 4; np++) {
                int r  = np * 16 + ((lane >> 4) << 3) + (lane & 7);
                int c4 = kt * 2 + ((lane >> 3) & 1);
                unsigned kh4[4], kl4[4];
                ldsm4(kh4, khb + SWZI(r, c4));
                ldsm4(kl4, klb + SWZI(r, c4));
#pragma unroll
                for (int ntl = 0; ntl < 2; ntl++)
                    mma16816(S[2 * np + ntl], qh4, kh4 + 2 * ntl);
#pragma unroll
                for (int ntl = 0; ntl < 2; ntl++)
                    mma16816(S[2 * np + ntl], ql4, kh4 + 2 * ntl);
#pragma unroll
                for (int ntl = 0; ntl < 2; ntl++)
                    mma16816(S[2 * np + ntl], qh4, kl4 + 2 * ntl);
            }
        }

        // ---- mask + row max + O rescale ----
        int r0 = rb + g, r1 = r0 + 8;
        if (diag) {
#pragma unroll
            for (int nt = 0; nt < 8; nt++) {
                int col = kb + nt * 8 + 2 * tq;
                if (col     > r0) S[nt][0] = -INFF;
                if (col + 1 > r0) S[nt][1] = -INFF;
                if (col     > r1) S[nt][2] = -INFF;
                if (col + 1 > r1) S[nt][3] = -INFF;
            }
        }
        float m0 = -INFF, m1 = -INFF;
#pragma unroll
        for (int nt = 0; nt < 8; nt++) {
            m0 = fmaxf(m0, fmaxf(S[nt][0], S[nt][1]));
            m1 = fmaxf(m1, fmaxf(S[nt][2], S[nt][3]));
        }
        m0 = fmaxf(m0, __shfl_xor_sync(0xffffffffu, m0, 1));
        m0 = fmaxf(m0, __shfl_xor_sync(0xffffffffu, m0, 2));
        m1 = fmaxf(m1, __shfl_xor_sync(0xffffffffu, m1, 1));
        m1 = fmaxf(m1, __shfl_xor_sync(0xffffffffu, m1, 2));
        float mn0 = fmaxf(mr[0], m0), mn1 = fmaxf(mr[1], m1);
        float sc0 = ex2f(mr[0] - mn0), sc1 = ex2f(mr[1] - mn1);
        mr[0] = mn0; mr[1] = mn1;
#pragma unroll
        for (int nt = 0; nt < 8; nt++) {
            O[nt][0] *= sc0; O[nt][1] *= sc0;
            O[nt][2] *= sc1; O[nt][3] *= sc1;
        }

        // ---- exp/pack interleaved with PV (P split in regs, V single) ----
        const uint32_t vhb = sb + SM_VH + buf * 8192;
        float rs0 = 0.f, rs1 = 0.f;
#pragma unroll
        for (int kt = 0; kt < 4; kt++) {
            unsigned ph[4], pl[4];
            {
                float e00 = ex2f(S[2*kt  ][0] - mn0);
                float e01 = ex2f(S[2*kt  ][1] - mn0);
                float e02 = ex2f(S[2*kt  ][2] - mn1);
                float e03 = ex2f(S[2*kt  ][3] - mn1);
                float e10 = ex2f(S[2*kt+1][0] - mn0);
                float e11 = ex2f(S[2*kt+1][1] - mn0);
                float e12 = ex2f(S[2*kt+1][2] - mn1);
                float e13 = ex2f(S[2*kt+1][3] - mn1);
                rs0 += (e00 + e01) + (e10 + e11);
                rs1 += (e02 + e03) + (e12 + e13);
                ph[0] = pkhl(e00, e01, pl[0]);
                ph[1] = pkhl(e02, e03, pl[1]);
                ph[2] = pkhl(e10, e11, pl[2]);
                ph[3] = pkhl(e12, e13, pl[3]);
            }
#pragma unroll
            for (int np = 0; np < 4; np++) {
                int r  = kt * 16 + (((lane >> 3) & 1) << 3) + (lane & 7);
                int c4 = np * 2 + (lane >> 4);
                unsigned vh4[4];
                ldsm4t(vh4, vhb + SWZI(r, c4));
#pragma unroll
                for (int ntl = 0; ntl < 2; ntl++)
                    mma16816(O[2 * np + ntl], ph, vh4 + 2 * ntl);
#pragma unroll
                for (int ntl = 0; ntl < 2; ntl++)
                    mma16816(O[2 * np + ntl], pl, vh4 + 2 * ntl);
            }
        }

        rs0 += __shfl_xor_sync(0xffffffffu, rs0, 1);
        rs0 += __shfl_xor_sync(0xffffffffu, rs0, 2);
        rs1 += __shfl_xor_sync(0xffffffffu, rs1, 1);
        rs1 += __shfl_xor_sync(0xffffffffu, rs1, 2);
        lr[0] = lr[0] * sc0 + rs0;
        lr[1] = lr[1] * sc1 + rs1;

        __syncthreads();
    }

    // ---- epilogue ----
    float i0 = 1.f / lr[0], i1 = 1.f / lr[1];
    size_t r0 = (size_t)(rb + g), r1 = r0 + 8;
#pragma unroll
    for (int nt = 0; nt < 8; nt++) {
        *(float2*)&out[gbase + r0 * AA + nt * 8 + 2 * tq] =
            make_float2(O[nt][0] * i0, O[nt][1] * i0);
        *(float2*)&out[gbase + r1 * AA + nt * 8 + 2 * tq] =
            make_float2(O[nt][2] * i1, O[nt][3] * i1);
    }
}

// ---------------------------------------------------------------------------
extern "C" void kernel_launch(void* const* d_in, const int* in_sizes, int n_in,
                              void* d_out, int out_size)
{
    const float* x  = (const float*)d_in[0];
    const float* Wq = (const float*)d_in[1];
    const float* Wk = (const float*)d_in[2];
    const float* Wv = (const float*)d_in[3];
    float* out = (float*)d_out;

    qkv_proj_kernel<<<BB * LL / 64, 256>>>(x, Wq, Wk, Wv);

    cudaFuncSetAttribute(attn_kernel,
                         cudaFuncAttributeMaxDynamicSharedMemorySize, SM_TOTAL);
    attn_kernel<<<256, 128, SM_TOTAL>>>(out);
}